// round 4
// baseline (speedup 1.0000x reference)
#include <cuda_runtime.h>
#include <cuda_bf16.h>

#define N_GENES 978
#define BATCH   8192
#define NNODES  (BATCH * N_GENES)   // 8,009,856
#define H1      2048
#define H2      100

// Scratch (static device globals — no runtime allocation)
__device__ float g_agg[NNODES];          // 32 MB: GCN aggregation buffer
__device__ float g_h[BATCH * H1];        // 64 MB: hidden layer
__device__ int   g_is64;                 // edges dtype flag (1 = int64)

// ---------------------------------------------------------------------------
// Detect edges dtype. View buffer as int32: for int64 indices < 2^31 every odd
// int32 (high word) is 0; for int32 data odd elements are random src indices.
// ---------------------------------------------------------------------------
__global__ void detect_dtype_kernel(const int* __restrict__ e32) {
    if (blockIdx.x != 0 || threadIdx.x != 0) return;
    int any = 0;
    for (int i = 0; i < 2048; i++) any |= e32[2 * i + 1];
    g_is64 = (any == 0) ? 1 : 0;
}

// ---------------------------------------------------------------------------
// Init: agg[i] = gcn_b (bias folded into init so scatter just accumulates;
// the GEMM applies ONLY relu on top of this)
// ---------------------------------------------------------------------------
__global__ void init_agg_kernel(float* __restrict__ agg,
                                const float* __restrict__ gcn_b, int n) {
    float b = __ldg(gcn_b);
    int i = blockIdx.x * blockDim.x + threadIdx.x;
    int stride = gridDim.x * blockDim.x;
    for (; i < n; i += stride) agg[i] = b;
}

// ---------------------------------------------------------------------------
// Scatter: agg[dst] += x[src] * gcn_w  over E edges.
// Uniform branch on detected dtype. 4 edges/thread (int32) or 2 (int64).
// ---------------------------------------------------------------------------
__global__ void scatter_kernel(const float* __restrict__ x,
                               const void* __restrict__ edges,
                               const float* __restrict__ gcn_w,
                               float* __restrict__ agg,
                               long long E) {
    const float w = __ldg(gcn_w);
    const bool is64 = (g_is64 != 0);
    const long long tidg = (long long)blockIdx.x * blockDim.x + threadIdx.x;
    const long long stride = (long long)gridDim.x * blockDim.x;

    if (!is64) {
        // int32 indices: process 4 edges per thread via int4 loads
        const int4* src4 = (const int4*)edges;
        const int4* dst4 = (const int4*)((const int*)edges + E);
        const long long quads = E >> 2;
        for (long long i = tidg; i < quads; i += stride) {
            int4 s = __ldg(&src4[i]);
            int4 d = __ldg(&dst4[i]);
            float v0 = __ldg(&x[s.x]) * w;
            float v1 = __ldg(&x[s.y]) * w;
            float v2 = __ldg(&x[s.z]) * w;
            float v3 = __ldg(&x[s.w]) * w;
            atomicAdd(&agg[d.x], v0);
            atomicAdd(&agg[d.y], v1);
            atomicAdd(&agg[d.z], v2);
            atomicAdd(&agg[d.w], v3);
        }
        // tail (E % 4)
        long long base = quads << 2;
        const int* srcs = (const int*)edges;
        const int* dsts = srcs + E;
        for (long long i = base + tidg; i < E; i += stride) {
            atomicAdd(&agg[dsts[i]], __ldg(&x[srcs[i]]) * w);
        }
    } else {
        // int64 indices: 2 edges per thread via 16B loads
        const longlong2* src2 = (const longlong2*)edges;
        const longlong2* dst2 = (const longlong2*)((const long long*)edges + E);
        const long long pairs = E >> 1;
        for (long long i = tidg; i < pairs; i += stride) {
            longlong2 s = __ldg(&src2[i]);
            longlong2 d = __ldg(&dst2[i]);
            float v0 = __ldg(&x[s.x]) * w;
            float v1 = __ldg(&x[s.y]) * w;
            atomicAdd(&agg[d.x], v0);
            atomicAdd(&agg[d.y], v1);
        }
        long long base = pairs << 1;
        const long long* srcs = (const long long*)edges;
        const long long* dsts = srcs + E;
        for (long long i = base + tidg; i < E; i += stride) {
            atomicAdd(&agg[dsts[i]], __ldg(&x[srcs[i]]) * w);
        }
    }
}

// ---------------------------------------------------------------------------
// Tiled fp32 GEMM: C[M,N] = act( actA(A[M,K]) @ B[K,N] + bias[N] )
//   RELU_A: A element -> relu(A)   (bias already folded into A upstream)
//   RELU_OUT: output relu
// 128x128 tile, 256 threads, 8x8 microtile, K-step 8, double-buffered SMEM.
// ---------------------------------------------------------------------------
template <bool RELU_A, bool RELU_OUT>
__global__ void __launch_bounds__(256, 2)
gemm128_kernel(const float* __restrict__ A, const float* __restrict__ B,
               const float* __restrict__ bias,
               float* __restrict__ C, int M, int N, int K) {
    __shared__ float As[2][8][128];
    __shared__ float Bs[2][8][128];

    const int tid = threadIdx.x;
    const int bm = blockIdx.y * 128;
    const int bn = blockIdx.x * 128;

    // A-tile load mapping: thread -> (row a_m, 4 consecutive k at a_k)
    const int a_m = tid & 127;
    const int a_k = (tid >> 7) * 4;        // 0 or 4
    // B-tile load mapping: thread -> (row b_k, 4 consecutive n at b_n)
    const int b_k = tid >> 5;              // 0..7
    const int b_n = (tid & 31) * 4;        // 0..124

    const int tx = tid & 15;               // 16 col-groups of 8
    const int ty = tid >> 4;               // 16 row-groups of 8

    float acc[8][8];
#pragma unroll
    for (int i = 0; i < 8; i++)
#pragma unroll
        for (int j = 0; j < 8; j++) acc[i][j] = 0.0f;

    const int nk = (K + 7) / 8;

    // Prologue: load stage 0
    {
        const int m = bm + a_m;
#pragma unroll
        for (int j = 0; j < 4; j++) {
            int k = a_k + j;
            float v = 0.0f;
            if (k < K && m < M) v = __ldg(&A[(long long)m * K + k]);
            if (RELU_A) v = fmaxf(v, 0.0f);
            As[0][a_k + j][a_m] = v;
        }
#pragma unroll
        for (int j = 0; j < 4; j++) {
            int n = bn + b_n + j;
            float v = 0.0f;
            if (b_k < K && n < N) v = __ldg(&B[(long long)b_k * N + n]);
            Bs[0][b_k][b_n + j] = v;
        }
    }
    __syncthreads();

    int buf = 0;
    for (int t = 0; t < nk; t++) {
        // Prefetch next stage into the other buffer (overlaps with compute)
        if (t + 1 < nk) {
            const int k0 = (t + 1) * 8;
            const int m = bm + a_m;
            const int nb = buf ^ 1;
#pragma unroll
            for (int j = 0; j < 4; j++) {
                int k = k0 + a_k + j;
                float v = 0.0f;
                if (k < K && m < M) v = __ldg(&A[(long long)m * K + k]);
                if (RELU_A) v = fmaxf(v, 0.0f);
                As[nb][a_k + j][a_m] = v;
            }
            const int kb = k0 + b_k;
#pragma unroll
            for (int j = 0; j < 4; j++) {
                int n = bn + b_n + j;
                float v = 0.0f;
                if (kb < K && n < N) v = __ldg(&B[(long long)kb * N + n]);
                Bs[nb][b_k][b_n + j] = v;
            }
        }

        // Compute current buffer
#pragma unroll
        for (int kk = 0; kk < 8; kk++) {
            float ar[8], br[8];
#pragma unroll
            for (int i = 0; i < 8; i++) ar[i] = As[buf][kk][ty * 8 + i];
#pragma unroll
            for (int j = 0; j < 8; j++) br[j] = Bs[buf][kk][tx * 8 + j];
#pragma unroll
            for (int i = 0; i < 8; i++)
#pragma unroll
                for (int j = 0; j < 8; j++)
                    acc[i][j] = fmaf(ar[i], br[j], acc[i][j]);
        }
        __syncthreads();
        buf ^= 1;
    }

    // Epilogue: bias + activation + store
#pragma unroll
    for (int i = 0; i < 8; i++) {
        int m = bm + ty * 8 + i;
        if (m >= M) continue;
#pragma unroll
        for (int j = 0; j < 8; j++) {
            int n = bn + tx * 8 + j;
            if (n >= N) continue;
            float v = acc[i][j] + __ldg(&bias[n]);
            if (RELU_OUT) v = fmaxf(v, 0.0f);
            C[(long long)m * N + n] = v;
        }
    }
}

// ---------------------------------------------------------------------------
// Launch
// Inputs (metadata order): 0 inputs f32[8192,978], 1 edges [2,E] (i32 or i64),
//   2 gcn_w f32[1,1], 3 gcn_b f32[1], 4 W1 f32[978,2048], 5 b1 f32[2048],
//   6 W2 f32[2048,100], 7 b2 f32[100].  Output: f32[8192,100].
// ---------------------------------------------------------------------------
extern "C" void kernel_launch(void* const* d_in, const int* in_sizes, int n_in,
                              void* d_out, int out_size) {
    const float* x     = (const float*)d_in[0];
    const void*  edges = d_in[1];
    const float* gcn_w = (const float*)d_in[2];
    const float* gcn_b = (const float*)d_in[3];
    const float* W1    = (const float*)d_in[4];
    const float* b1    = (const float*)d_in[5];
    const float* W2    = (const float*)d_in[6];
    const float* b2    = (const float*)d_in[7];
    float*       out   = (float*)d_out;

    const long long E = (long long)in_sizes[1] / 2;

    float* agg;  cudaGetSymbolAddress((void**)&agg, g_agg);
    float* h;    cudaGetSymbolAddress((void**)&h,   g_h);

    // 0) detect edges dtype (int32 vs int64), device-side, capture-safe
    detect_dtype_kernel<<<1, 1>>>((const int*)edges);

    // 1) agg = gcn_b
    {
        int threads = 256;
        int blocks = (NNODES + threads - 1) / threads;
        init_agg_kernel<<<blocks, threads>>>(agg, gcn_b, NNODES);
    }

    // 2) agg[dst] += x[src] * w
    {
        int threads = 256;
        long long work = E >> 2;   // per-thread granularity (int32 fast path)
        int blocks = (int)((work + threads - 1) / threads);
        if (blocks < 1) blocks = 1;
        scatter_kernel<<<blocks, threads>>>(x, edges, gcn_w, agg, E);
    }

    // 3) h = relu( relu(agg) @ W1 + b1 )   [8192 x 2048]  (agg already has +b)
    {
        dim3 grid(H1 / 128, BATCH / 128);   // (16, 64)
        gemm128_kernel<true, true><<<grid, 256>>>(agg, W1, b1, h,
                                                  BATCH, H1, N_GENES);
    }

    // 4) out = h @ W2 + b2                 [8192 x 100]
    {
        dim3 grid((H2 + 127) / 128, BATCH / 128);  // (1, 64)
        gemm128_kernel<false, false><<<grid, 256>>>(h, W2, b2, out,
                                                    BATCH, H2, H1);
    }
}

// round 6
// speedup vs baseline: 1.1225x; 1.1225x over previous
#include <cuda_runtime.h>
#include <cuda_bf16.h>

#define N_GENES 978
#define BATCH   8192
#define NNODES  (BATCH * N_GENES)   // 8,009,856
#define H1      2048
#define H2      100
#define GEMM2_KS 4                  // split-K factor for GEMM2

// Scratch (static device globals — no runtime allocation)
__device__ float g_agg[NNODES];          // 32 MB: GCN aggregation buffer
__device__ float g_h[BATCH * H1];        // 64 MB: hidden layer
__device__ int   g_is64;                 // edges dtype flag (1 = int64)

// ---------------------------------------------------------------------------
// Detect edges dtype. View buffer as int32: for int64 indices < 2^31 every odd
// int32 (high word) is 0; for int32 data odd elements are random src indices.
// ---------------------------------------------------------------------------
__global__ void detect_dtype_kernel(const int* __restrict__ e32) {
    if (blockIdx.x != 0 || threadIdx.x != 0) return;
    int any = 0;
    for (int i = 0; i < 2048; i++) any |= e32[2 * i + 1];
    g_is64 = (any == 0) ? 1 : 0;
}

// ---------------------------------------------------------------------------
// Init: agg[i] = gcn_b (bias folded here; GEMM1 applies only relu on top)
// ---------------------------------------------------------------------------
__global__ void init_agg_kernel(float* __restrict__ agg,
                                const float* __restrict__ gcn_b, int n) {
    float b = __ldg(gcn_b);
    int i = blockIdx.x * blockDim.x + threadIdx.x;
    int stride = gridDim.x * blockDim.x;
    for (; i < n; i += stride) agg[i] = b;
}

// out[m,n] = b2[n]  (bias pre-init so GEMM2 split-K blocks can atomicAdd)
__global__ void init_out_kernel(float* __restrict__ out,
                                const float* __restrict__ b2, int M, int N) {
    int i = blockIdx.x * blockDim.x + threadIdx.x;
    int stride = gridDim.x * blockDim.x;
    int total = M * N;
    for (; i < total; i += stride) out[i] = __ldg(&b2[i % N]);
}

// ---------------------------------------------------------------------------
// Scatter: agg[dst] += x[src] * gcn_w  over E edges.
// ---------------------------------------------------------------------------
__global__ void scatter_kernel(const float* __restrict__ x,
                               const void* __restrict__ edges,
                               const float* __restrict__ gcn_w,
                               float* __restrict__ agg,
                               long long E) {
    const float w = __ldg(gcn_w);
    const bool is64 = (g_is64 != 0);
    const long long tidg = (long long)blockIdx.x * blockDim.x + threadIdx.x;
    const long long stride = (long long)gridDim.x * blockDim.x;

    if (!is64) {
        const int4* src4 = (const int4*)edges;
        const int4* dst4 = (const int4*)((const int*)edges + E);
        const long long quads = E >> 2;
        for (long long i = tidg; i < quads; i += stride) {
            int4 s = __ldg(&src4[i]);
            int4 d = __ldg(&dst4[i]);
            float v0 = __ldg(&x[s.x]) * w;
            float v1 = __ldg(&x[s.y]) * w;
            float v2 = __ldg(&x[s.z]) * w;
            float v3 = __ldg(&x[s.w]) * w;
            atomicAdd(&agg[d.x], v0);
            atomicAdd(&agg[d.y], v1);
            atomicAdd(&agg[d.z], v2);
            atomicAdd(&agg[d.w], v3);
        }
        long long base = quads << 2;
        const int* srcs = (const int*)edges;
        const int* dsts = srcs + E;
        for (long long i = base + tidg; i < E; i += stride)
            atomicAdd(&agg[dsts[i]], __ldg(&x[srcs[i]]) * w);
    } else {
        const longlong2* src2 = (const longlong2*)edges;
        const longlong2* dst2 = (const longlong2*)((const long long*)edges + E);
        const long long pairs = E >> 1;
        for (long long i = tidg; i < pairs; i += stride) {
            longlong2 s = __ldg(&src2[i]);
            longlong2 d = __ldg(&dst2[i]);
            atomicAdd(&agg[d.x], __ldg(&x[s.x]) * w);
            atomicAdd(&agg[d.y], __ldg(&x[s.y]) * w);
        }
        long long base = pairs << 1;
        const long long* srcs = (const long long*)edges;
        const long long* dsts = srcs + E;
        for (long long i = base + tidg; i < E; i += stride)
            atomicAdd(&agg[dsts[i]], __ldg(&x[srcs[i]]) * w);
    }
}

// ---------------------------------------------------------------------------
// GEMM1: 128x128 tile, 256 threads, 8x8 micro, double-buffered SMEM,
// float4 (LDS.128) inner-loop reads -> 4 LDS per 64 FMA instead of 16.
//   RELU_A on A load; bias + RELU_OUT in epilogue.
// ---------------------------------------------------------------------------
template <bool RELU_A, bool RELU_OUT>
__global__ void __launch_bounds__(256, 2)
gemm128_kernel(const float* __restrict__ A, const float* __restrict__ B,
               const float* __restrict__ bias,
               float* __restrict__ C, int M, int N, int K) {
    __shared__ float As[2][8][128];
    __shared__ float Bs[2][8][128];

    const int tid = threadIdx.x;
    const int bm = blockIdx.y * 128;
    const int bn = blockIdx.x * 128;

    const int a_m = tid & 127;
    const int a_k = (tid >> 7) * 4;        // 0 or 4
    const int b_k = tid >> 5;              // 0..7
    const int b_n = (tid & 31) * 4;        // 0..124

    const int tx = tid & 15;               // 16 col-groups of 8
    const int ty = tid >> 4;               // 16 row-groups of 8

    float acc[8][8];
#pragma unroll
    for (int i = 0; i < 8; i++)
#pragma unroll
        for (int j = 0; j < 8; j++) acc[i][j] = 0.0f;

    const int nk = (K + 7) / 8;

    // Prologue: stage 0
    {
        const int m = bm + a_m;
#pragma unroll
        for (int j = 0; j < 4; j++) {
            int k = a_k + j;
            float v = 0.0f;
            if (k < K && m < M) v = __ldg(&A[(long long)m * K + k]);
            if (RELU_A) v = fmaxf(v, 0.0f);
            As[0][a_k + j][a_m] = v;
        }
#pragma unroll
        for (int j = 0; j < 4; j++) {
            int n = bn + b_n + j;
            float v = 0.0f;
            if (b_k < K && n < N) v = __ldg(&B[(long long)b_k * N + n]);
            Bs[0][b_k][b_n + j] = v;
        }
    }
    __syncthreads();

    int buf = 0;
    for (int t = 0; t < nk; t++) {
        if (t + 1 < nk) {
            const int k0 = (t + 1) * 8;
            const int m = bm + a_m;
            const int nb = buf ^ 1;
#pragma unroll
            for (int j = 0; j < 4; j++) {
                int k = k0 + a_k + j;
                float v = 0.0f;
                if (k < K && m < M) v = __ldg(&A[(long long)m * K + k]);
                if (RELU_A) v = fmaxf(v, 0.0f);
                As[nb][a_k + j][a_m] = v;
            }
            const int kb = k0 + b_k;
#pragma unroll
            for (int j = 0; j < 4; j++) {
                int n = bn + b_n + j;
                float v = 0.0f;
                if (kb < K && n < N) v = __ldg(&B[(long long)kb * N + n]);
                Bs[nb][b_k][b_n + j] = v;
            }
        }

#pragma unroll
        for (int kk = 0; kk < 8; kk++) {
            const float4* ap = (const float4*)(&As[buf][kk][0]);
            const float4* bp = (const float4*)(&Bs[buf][kk][0]);
            float4 a0 = ap[ty * 2], a1 = ap[ty * 2 + 1];
            float4 b0 = bp[tx * 2], b1 = bp[tx * 2 + 1];
            float ar[8] = {a0.x, a0.y, a0.z, a0.w, a1.x, a1.y, a1.z, a1.w};
            float br[8] = {b0.x, b0.y, b0.z, b0.w, b1.x, b1.y, b1.z, b1.w};
#pragma unroll
            for (int i = 0; i < 8; i++)
#pragma unroll
                for (int j = 0; j < 8; j++)
                    acc[i][j] = fmaf(ar[i], br[j], acc[i][j]);
        }
        __syncthreads();
        buf ^= 1;
    }

    // Epilogue
#pragma unroll
    for (int i = 0; i < 8; i++) {
        int m = bm + ty * 8 + i;
        if (m >= M) continue;
#pragma unroll
        for (int j = 0; j < 8; j++) {
            int n = bn + tx * 8 + j;
            if (n >= N) continue;
            float v = acc[i][j] + __ldg(&bias[n]);
            if (RELU_OUT) v = fmaxf(v, 0.0f);
            C[(long long)m * N + n] = v;
        }
    }
}

// ---------------------------------------------------------------------------
// GEMM2 (split-K): C[8192,100] += h[8192,2048] @ W2[2048,100]
// Tile: 64 rows x 128 cols (N padded in smem; guarded at 100), micro 4x8,
// 256 threads. Grid = (KS, M/64) = (4, 128) = 512 blocks -> full chip.
// Partial results atomicAdd'ed onto bias-initialized C.
// ---------------------------------------------------------------------------
__global__ void __launch_bounds__(256, 2)
gemm2_splitk_kernel(const float* __restrict__ A, const float* __restrict__ B,
                    float* __restrict__ C) {
    const int M = BATCH, N = H2, K = H1;
    const int KCHUNK = K / GEMM2_KS;     // 512

    __shared__ float As[2][8][64];
    __shared__ float Bs[2][8][128];

    const int tid = threadIdx.x;
    const int bm = blockIdx.y * 64;
    const int kbase = blockIdx.x * KCHUNK;

    // A-tile: 8k x 64m = 512 elems, 2 per thread (2 consecutive k)
    const int a_m = tid & 63;
    const int a_k = (tid >> 6) * 2;       // 0,2,4,6
    // B-tile: 8k x 128n (only first 100 valid)
    const int b_k = tid >> 5;             // 0..7
    const int b_n = (tid & 31) * 4;       // 0..124

    const int tx = tid & 15;              // 8 cols each
    const int ty = tid >> 4;              // 4 rows each

    float acc[4][8];
#pragma unroll
    for (int i = 0; i < 4; i++)
#pragma unroll
        for (int j = 0; j < 8; j++) acc[i][j] = 0.0f;

    const int nk = KCHUNK / 8;            // 64

    // Prologue
    {
#pragma unroll
        for (int j = 0; j < 2; j++) {
            int k = kbase + a_k + j;
            As[0][a_k + j][a_m] = __ldg(&A[(long long)(bm + a_m) * K + k]);
        }
        int kb = kbase + b_k;
#pragma unroll
        for (int j = 0; j < 4; j++) {
            int n = b_n + j;
            Bs[0][b_k][n] = (n < N) ? __ldg(&B[(long long)kb * N + n]) : 0.0f;
        }
    }
    __syncthreads();

    int buf = 0;
    for (int t = 0; t < nk; t++) {
        if (t + 1 < nk) {
            const int k0 = kbase + (t + 1) * 8;
            const int nb = buf ^ 1;
#pragma unroll
            for (int j = 0; j < 2; j++)
                As[nb][a_k + j][a_m] = __ldg(&A[(long long)(bm + a_m) * K + k0 + a_k + j]);
            const int kb = k0 + b_k;
#pragma unroll
            for (int j = 0; j < 4; j++) {
                int n = b_n + j;
                Bs[nb][b_k][n] = (n < N) ? __ldg(&B[(long long)kb * N + n]) : 0.0f;
            }
        }

#pragma unroll
        for (int kk = 0; kk < 8; kk++) {
            const float4* ap = (const float4*)(&As[buf][kk][0]);
            const float4* bp = (const float4*)(&Bs[buf][kk][0]);
            float4 a0 = ap[ty];                       // 4 rows
            float4 b0 = bp[tx * 2], b1 = bp[tx * 2 + 1];
            float ar[4] = {a0.x, a0.y, a0.z, a0.w};
            float br[8] = {b0.x, b0.y, b0.z, b0.w, b1.x, b1.y, b1.z, b1.w};
#pragma unroll
            for (int i = 0; i < 4; i++)
#pragma unroll
                for (int j = 0; j < 8; j++)
                    acc[i][j] = fmaf(ar[i], br[j], acc[i][j]);
        }
        __syncthreads();
        buf ^= 1;
    }

    // Epilogue: atomic accumulate (C pre-initialized with bias)
#pragma unroll
    for (int i = 0; i < 4; i++) {
        int m = bm + ty * 4 + i;
#pragma unroll
        for (int j = 0; j < 8; j++) {
            int n = tx * 8 + j;
            if (n < N) atomicAdd(&C[(long long)m * N + n], acc[i][j]);
        }
    }
}

// ---------------------------------------------------------------------------
// Launch
// ---------------------------------------------------------------------------
extern "C" void kernel_launch(void* const* d_in, const int* in_sizes, int n_in,
                              void* d_out, int out_size) {
    const float* x     = (const float*)d_in[0];
    const void*  edges = d_in[1];
    const float* gcn_w = (const float*)d_in[2];
    const float* gcn_b = (const float*)d_in[3];
    const float* W1    = (const float*)d_in[4];
    const float* b1    = (const float*)d_in[5];
    const float* W2    = (const float*)d_in[6];
    const float* b2    = (const float*)d_in[7];
    float*       out   = (float*)d_out;

    const long long E = (long long)in_sizes[1] / 2;

    float* agg;  cudaGetSymbolAddress((void**)&agg, g_agg);
    float* h;    cudaGetSymbolAddress((void**)&h,   g_h);

    // 0) detect edges dtype
    detect_dtype_kernel<<<1, 1>>>((const int*)edges);

    // 1) agg = gcn_b ; out = b2
    {
        int threads = 256;
        init_agg_kernel<<<(NNODES + threads - 1) / threads, threads>>>(agg, gcn_b, NNODES);
        init_out_kernel<<<(BATCH * H2 + threads - 1) / threads, threads>>>(out, b2, BATCH, H2);
    }

    // 2) agg[dst] += x[src] * w
    {
        int threads = 256;
        long long work = E >> 2;
        int blocks = (int)((work + threads - 1) / threads);
        if (blocks < 1) blocks = 1;
        scatter_kernel<<<blocks, threads>>>(x, edges, gcn_w, agg, E);
    }

    // 3) h = relu( relu(agg) @ W1 + b1 )   [8192 x 2048]
    {
        dim3 grid(H1 / 128, BATCH / 128);   // (16, 64)
        gemm128_kernel<true, true><<<grid, 256>>>(agg, W1, b1, h,
                                                  BATCH, H1, N_GENES);
    }

    // 4) out += h @ W2   (bias already in out)  [8192 x 100]
    {
        dim3 grid(GEMM2_KS, BATCH / 64);    // (4, 128) = 512 blocks
        gemm2_splitk_kernel<<<grid, 256>>>(h, W2, out);
    }
}

// round 7
// speedup vs baseline: 1.9004x; 1.6931x over previous
#include <cuda_runtime.h>
#include <cuda_bf16.h>
#include <cstdint>

#define N_GENES 978
#define BATCH   8192
#define NNODES  (BATCH * N_GENES)   // 8,009,856
#define H1      2048
#define H2      100
#define GEMM2_KS 4

// Scratch (static device globals — no runtime allocation)
__device__ float g_agg[NNODES];          // 32 MB: GCN aggregation buffer
__device__ float g_h[BATCH * H1];        // 64 MB: hidden layer
__device__ int   g_is64;                 // edges dtype flag (1 = int64)

// ---------------------------------------------------------------------------
// Detect edges dtype (parallel: 1 warp, 64 samples of odd int32 words)
// ---------------------------------------------------------------------------
__global__ void detect_dtype_kernel(const int* __restrict__ e32) {
    int l = threadIdx.x;   // 32 threads
    int v = e32[2 * l + 1] | e32[2 * (l + 32) + 1];
    int any = __any_sync(0xFFFFFFFFu, v != 0);
    if (l == 0) g_is64 = any ? 0 : 1;
}

// ---------------------------------------------------------------------------
// Init: agg[i] = gcn_b
// ---------------------------------------------------------------------------
__global__ void init_agg_kernel(float* __restrict__ agg,
                                const float* __restrict__ gcn_b, int n) {
    float b = __ldg(gcn_b);
    int i = blockIdx.x * blockDim.x + threadIdx.x;
    int stride = gridDim.x * blockDim.x;
    for (; i < n; i += stride) agg[i] = b;
}

// out[m,n] = b2[n]
__global__ void init_out_kernel(float* __restrict__ out,
                                const float* __restrict__ b2, int M, int N) {
    int i = blockIdx.x * blockDim.x + threadIdx.x;
    int stride = gridDim.x * blockDim.x;
    int total = M * N;
    for (; i < total; i += stride) out[i] = __ldg(&b2[i % N]);
}

// ---------------------------------------------------------------------------
// Scatter: agg[dst] += x[src] * gcn_w
// ---------------------------------------------------------------------------
__global__ void scatter_kernel(const float* __restrict__ x,
                               const void* __restrict__ edges,
                               const float* __restrict__ gcn_w,
                               float* __restrict__ agg,
                               long long E) {
    const float w = __ldg(gcn_w);
    const bool is64 = (g_is64 != 0);
    const long long tidg = (long long)blockIdx.x * blockDim.x + threadIdx.x;
    const long long stride = (long long)gridDim.x * blockDim.x;

    if (!is64) {
        const int4* src4 = (const int4*)edges;
        const int4* dst4 = (const int4*)((const int*)edges + E);
        const long long quads = E >> 2;
        for (long long i = tidg; i < quads; i += stride) {
            int4 s = __ldg(&src4[i]);
            int4 d = __ldg(&dst4[i]);
            float v0 = __ldg(&x[s.x]) * w;
            float v1 = __ldg(&x[s.y]) * w;
            float v2 = __ldg(&x[s.z]) * w;
            float v3 = __ldg(&x[s.w]) * w;
            atomicAdd(&agg[d.x], v0);
            atomicAdd(&agg[d.y], v1);
            atomicAdd(&agg[d.z], v2);
            atomicAdd(&agg[d.w], v3);
        }
        long long base = quads << 2;
        const int* srcs = (const int*)edges;
        const int* dsts = srcs + E;
        for (long long i = base + tidg; i < E; i += stride)
            atomicAdd(&agg[dsts[i]], __ldg(&x[srcs[i]]) * w);
    } else {
        const longlong2* src2 = (const longlong2*)edges;
        const longlong2* dst2 = (const longlong2*)((const long long*)edges + E);
        const long long pairs = E >> 1;
        for (long long i = tidg; i < pairs; i += stride) {
            longlong2 s = __ldg(&src2[i]);
            longlong2 d = __ldg(&dst2[i]);
            atomicAdd(&agg[d.x], __ldg(&x[s.x]) * w);
            atomicAdd(&agg[d.y], __ldg(&x[s.y]) * w);
        }
        long long base = pairs << 1;
        const long long* srcs = (const long long*)edges;
        const long long* dsts = srcs + E;
        for (long long i = base + tidg; i < E; i += stride)
            atomicAdd(&agg[dsts[i]], __ldg(&x[srcs[i]]) * w);
    }
}

// ---------------------------------------------------------------------------
// mma.sync / ldmatrix helpers
// ---------------------------------------------------------------------------
__device__ __forceinline__ void ldsm_x4(uint32_t* r, uint32_t addr) {
    asm volatile("ldmatrix.sync.aligned.m8n8.x4.shared.b16 {%0,%1,%2,%3},[%4];"
                 : "=r"(r[0]), "=r"(r[1]), "=r"(r[2]), "=r"(r[3]) : "r"(addr));
}
__device__ __forceinline__ void ldsm_x4t(uint32_t* r, uint32_t addr) {
    asm volatile("ldmatrix.sync.aligned.m8n8.x4.trans.shared.b16 {%0,%1,%2,%3},[%4];"
                 : "=r"(r[0]), "=r"(r[1]), "=r"(r[2]), "=r"(r[3]) : "r"(addr));
}
__device__ __forceinline__ void mma16816(float* c, const uint32_t* a, const uint32_t* b) {
    asm volatile(
        "mma.sync.aligned.m16n8k16.row.col.f32.bf16.bf16.f32 "
        "{%0,%1,%2,%3},{%4,%5,%6,%7},{%8,%9},{%0,%1,%2,%3};"
        : "+f"(c[0]), "+f"(c[1]), "+f"(c[2]), "+f"(c[3])
        : "r"(a[0]), "r"(a[1]), "r"(a[2]), "r"(a[3]), "r"(b[0]), "r"(b[1]));
}

// ---------------------------------------------------------------------------
// GEMM1 (tensor core, bf16x3 split): h = relu( relu(agg) @ W1 + b1 )
// Tile 128x128x32, 256 threads (8 warps: 4m x 2n), single smem buffer with
// register-prefetch of the next tile's global loads.
// Split: v = hi + lo (two bf16 planes); acc += Ahi*Bhi + Ahi*Blo + Alo*Bhi.
// ---------------------------------------------------------------------------
#define G1_BM 128
#define G1_BN 128
#define G1_BK 32
#define A_PAD 40    // 32 -> 40 bf16 per row (80B), conflict-free ldmatrix
#define B_PAD 136   // 128 -> 136 bf16 per row (272B)

__global__ void __launch_bounds__(256, 1)
gemm1_mma_kernel(const float* __restrict__ A, const float* __restrict__ B,
                 const float* __restrict__ bias, float* __restrict__ C,
                 int M, int N, int K) {
    __shared__ __nv_bfloat16 As[2][G1_BM][A_PAD];  // [hi/lo][m][k]
    __shared__ __nv_bfloat16 Bs[2][G1_BK][B_PAD];  // [hi/lo][k][n]

    const int tid = threadIdx.x;
    const int l = tid & 31;
    const int wid = tid >> 5;
    const int warp_m = wid & 3;          // 0..3 -> 32 rows each
    const int warp_n = wid >> 2;         // 0..1 -> 64 cols each
    const int bm = blockIdx.y * G1_BM;
    const int bn = blockIdx.x * G1_BN;

    // ldmatrix lane address components (shared by A and B patterns)
    const int lrow = (l & 7) + ((l >> 3) & 1) * 8;
    const int lcol8 = ((l >> 4) & 1) * 8;

    const uint32_t as_base = (uint32_t)__cvta_generic_to_shared(&As[0][0][0]);
    const uint32_t bs_base = (uint32_t)__cvta_generic_to_shared(&Bs[0][0][0]);
    const uint32_t as_plane = G1_BM * A_PAD * 2;   // bytes between hi and lo
    const uint32_t bs_plane = G1_BK * B_PAD * 2;
    const uint32_t a_addr = as_base + ((warp_m * 32 + lrow) * A_PAD + lcol8) * 2;
    const uint32_t b_addr = bs_base + (lrow * B_PAD + warp_n * 64 + lcol8) * 2;

    float acc[2][8][4];
#pragma unroll
    for (int f = 0; f < 2; f++)
#pragma unroll
        for (int j = 0; j < 8; j++)
#pragma unroll
            for (int i = 0; i < 4; i++) acc[f][j][i] = 0.0f;

    const int nk = (K + G1_BK - 1) / G1_BK;

    float a_pref[16], b_pref[16];

    // ---- global tile load into registers (coalesced: lane-consecutive) ----
    auto load_tiles = [&](int t) {
#pragma unroll
        for (int i = 0; i < 16; i++) {
            int e = 256 * i + tid;           // A: 128x32
            int row = e >> 5, k = e & 31;
            int gk = t * G1_BK + k;
            a_pref[i] = (gk < K) ? __ldg(&A[(long long)(bm + row) * K + gk]) : 0.0f;
        }
#pragma unroll
        for (int i = 0; i < 16; i++) {
            int e = 256 * i + tid;           // B: 32x128
            int krow = e >> 7, n = e & 127;
            int gk = t * G1_BK + krow;
            b_pref[i] = (gk < K) ? __ldg(&B[(long long)gk * N + bn + n]) : 0.0f;
        }
    };

    // ---- split + store to smem ----
    auto store_tiles = [&]() {
#pragma unroll
        for (int i = 0; i < 16; i++) {
            int e = 256 * i + tid;
            int row = e >> 5, k = e & 31;
            float v = fmaxf(a_pref[i], 0.0f);              // relu(A) fused
            __nv_bfloat16 hi = __float2bfloat16(v);
            __nv_bfloat16 lo = __float2bfloat16(v - __bfloat162float(hi));
            As[0][row][k] = hi;
            As[1][row][k] = lo;
        }
#pragma unroll
        for (int i = 0; i < 16; i++) {
            int e = 256 * i + tid;
            int krow = e >> 7, n = e & 127;
            float v = b_pref[i];
            __nv_bfloat16 hi = __float2bfloat16(v);
            __nv_bfloat16 lo = __float2bfloat16(v - __bfloat162float(hi));
            Bs[0][krow][n] = hi;
            Bs[1][krow][n] = lo;
        }
    };

    load_tiles(0);
    store_tiles();
    __syncthreads();

    for (int t = 0; t < nk; t++) {
        if (t + 1 < nk) load_tiles(t + 1);   // LDG overlapped with mma below

#pragma unroll
        for (int ks = 0; ks < 2; ks++) {
            uint32_t ah[2][4], al[2][4];
#pragma unroll
            for (int f = 0; f < 2; f++) {
                uint32_t off = ((f * 16) * A_PAD + ks * 16) * 2;
                ldsm_x4(ah[f], a_addr + off);
                ldsm_x4(al[f], a_addr + as_plane + off);
            }
#pragma unroll
            for (int g = 0; g < 4; g++) {
                uint32_t bh[4], bl[4];
                uint32_t off = ((ks * 16) * B_PAD + g * 16) * 2;
                ldsm_x4t(bh, b_addr + off);
                ldsm_x4t(bl, b_addr + bs_plane + off);
#pragma unroll
                for (int f = 0; f < 2; f++) {
                    mma16816(acc[f][2 * g],     ah[f], bh);
                    mma16816(acc[f][2 * g],     ah[f], bl);
                    mma16816(acc[f][2 * g],     al[f], bh);
                    mma16816(acc[f][2 * g + 1], ah[f], bh + 2);
                    mma16816(acc[f][2 * g + 1], ah[f], bl + 2);
                    mma16816(acc[f][2 * g + 1], al[f], bh + 2);
                }
            }
        }
        __syncthreads();
        if (t + 1 < nk) {
            store_tiles();
            __syncthreads();
        }
    }

    // ---- epilogue: bias + relu, float2 stores ----
#pragma unroll
    for (int f = 0; f < 2; f++) {
#pragma unroll
        for (int j = 0; j < 8; j++) {
            int m0 = bm + warp_m * 32 + f * 16 + (l >> 2);
            int n0 = bn + warp_n * 64 + j * 8 + (l & 3) * 2;
            float bb0 = __ldg(&bias[n0]);
            float bb1 = __ldg(&bias[n0 + 1]);
            float2 v0, v1;
            v0.x = fmaxf(acc[f][j][0] + bb0, 0.0f);
            v0.y = fmaxf(acc[f][j][1] + bb1, 0.0f);
            v1.x = fmaxf(acc[f][j][2] + bb0, 0.0f);
            v1.y = fmaxf(acc[f][j][3] + bb1, 0.0f);
            *(float2*)&C[(long long)m0 * N + n0] = v0;
            *(float2*)&C[(long long)(m0 + 8) * N + n0] = v1;
        }
    }
}

// ---------------------------------------------------------------------------
// GEMM2 (split-K SIMT): C[8192,100] += h[8192,2048] @ W2[2048,100]
// ---------------------------------------------------------------------------
__global__ void __launch_bounds__(256, 2)
gemm2_splitk_kernel(const float* __restrict__ A, const float* __restrict__ B,
                    float* __restrict__ C) {
    const int M = BATCH, N = H2, K = H1;
    const int KCHUNK = K / GEMM2_KS;     // 512

    __shared__ float As[2][8][64];
    __shared__ float Bs[2][8][128];

    const int tid = threadIdx.x;
    const int bm = blockIdx.y * 64;
    const int kbase = blockIdx.x * KCHUNK;

    const int a_m = tid & 63;
    const int a_k = (tid >> 6) * 2;
    const int b_k = tid >> 5;
    const int b_n = (tid & 31) * 4;

    const int tx = tid & 15;
    const int ty = tid >> 4;

    float acc[4][8];
#pragma unroll
    for (int i = 0; i < 4; i++)
#pragma unroll
        for (int j = 0; j < 8; j++) acc[i][j] = 0.0f;

    const int nk = KCHUNK / 8;

    {
#pragma unroll
        for (int j = 0; j < 2; j++) {
            int k = kbase + a_k + j;
            As[0][a_k + j][a_m] = __ldg(&A[(long long)(bm + a_m) * K + k]);
        }
        int kb = kbase + b_k;
#pragma unroll
        for (int j = 0; j < 4; j++) {
            int n = b_n + j;
            Bs[0][b_k][n] = (n < N) ? __ldg(&B[(long long)kb * N + n]) : 0.0f;
        }
    }
    __syncthreads();

    int buf = 0;
    for (int t = 0; t < nk; t++) {
        if (t + 1 < nk) {
            const int k0 = kbase + (t + 1) * 8;
            const int nb = buf ^ 1;
#pragma unroll
            for (int j = 0; j < 2; j++)
                As[nb][a_k + j][a_m] = __ldg(&A[(long long)(bm + a_m) * K + k0 + a_k + j]);
            const int kb = k0 + b_k;
#pragma unroll
            for (int j = 0; j < 4; j++) {
                int n = b_n + j;
                Bs[nb][b_k][n] = (n < N) ? __ldg(&B[(long long)kb * N + n]) : 0.0f;
            }
        }

#pragma unroll
        for (int kk = 0; kk < 8; kk++) {
            const float4* ap = (const float4*)(&As[buf][kk][0]);
            const float4* bp = (const float4*)(&Bs[buf][kk][0]);
            float4 a0 = ap[ty];
            float4 b0 = bp[tx * 2], b1 = bp[tx * 2 + 1];
            float ar[4] = {a0.x, a0.y, a0.z, a0.w};
            float br[8] = {b0.x, b0.y, b0.z, b0.w, b1.x, b1.y, b1.z, b1.w};
#pragma unroll
            for (int i = 0; i < 4; i++)
#pragma unroll
                for (int j = 0; j < 8; j++)
                    acc[i][j] = fmaf(ar[i], br[j], acc[i][j]);
        }
        __syncthreads();
        buf ^= 1;
    }

#pragma unroll
    for (int i = 0; i < 4; i++) {
        int m = bm + ty * 4 + i;
#pragma unroll
        for (int j = 0; j < 8; j++) {
            int n = tx * 8 + j;
            if (n < N) atomicAdd(&C[(long long)m * N + n], acc[i][j]);
        }
    }
}

// ---------------------------------------------------------------------------
// Launch
// ---------------------------------------------------------------------------
extern "C" void kernel_launch(void* const* d_in, const int* in_sizes, int n_in,
                              void* d_out, int out_size) {
    const float* x     = (const float*)d_in[0];
    const void*  edges = d_in[1];
    const float* gcn_w = (const float*)d_in[2];
    const float* gcn_b = (const float*)d_in[3];
    const float* W1    = (const float*)d_in[4];
    const float* b1    = (const float*)d_in[5];
    const float* W2    = (const float*)d_in[6];
    const float* b2    = (const float*)d_in[7];
    float*       out   = (float*)d_out;

    const long long E = (long long)in_sizes[1] / 2;

    float* agg;  cudaGetSymbolAddress((void**)&agg, g_agg);
    float* h;    cudaGetSymbolAddress((void**)&h,   g_h);

    // 0) detect edges dtype
    detect_dtype_kernel<<<1, 32>>>((const int*)edges);

    // 1) agg = gcn_b ; out = b2
    {
        int threads = 256;
        init_agg_kernel<<<(NNODES + threads - 1) / threads, threads>>>(agg, gcn_b, NNODES);
        init_out_kernel<<<(BATCH * H2 + threads - 1) / threads, threads>>>(out, b2, BATCH, H2);
    }

    // 2) agg[dst] += x[src] * w
    {
        int threads = 256;
        long long work = E >> 2;
        int blocks = (int)((work + threads - 1) / threads);
        if (blocks < 1) blocks = 1;
        scatter_kernel<<<blocks, threads>>>(x, edges, gcn_w, agg, E);
    }

    // 3) h = relu( relu(agg) @ W1 + b1 )   [8192 x 2048]  (tensor cores)
    {
        dim3 grid(H1 / G1_BN, BATCH / G1_BM);   // (16, 64)
        gemm1_mma_kernel<<<grid, 256>>>(agg, W1, b1, h, BATCH, H1, N_GENES);
    }

    // 4) out += h @ W2   (bias already in out)  [8192 x 100]
    {
        dim3 grid(GEMM2_KS, BATCH / 64);        // (4, 128)
        gemm2_splitk_kernel<<<grid, 256>>>(h, W2, out);
    }
}